// round 10
// baseline (speedup 1.0000x reference)
#include <cuda_runtime.h>

// ---------------------------------------------------------------------------
// NeuralSplineFlow3D fused kernel — fp32 FFMA2, 512 threads / 256 points,
// thread = 4 pts x 8 outs (hidden), 4 pts x 10 cols (out), split splines.
// ---------------------------------------------------------------------------

#define THREADS   512
#define COLS      256
#define PW        68           // smem pitch (floats) for 64-wide hidden weights
#define PO        80           // smem pitch (floats) for output weights (2x37+pad)
#define TBc       5.0f
#define MINc      0.001f
#define LOGZc     (-2.7568155996140194f)   // -1.5*log(2*pi)
#define DCONSTf   (0.5397424697f)          // log(exp(1-0.001)-1)

// smem layout (float offsets)
#define SM_WT     0                         // 4*64*68 = 17408
#define SM_WO     (SM_WT + 4*64*PW)         // 64*80   = 5120
#define SM_WIN    (SM_WO + 64*PO)           // 64
#define SM_BIN    (SM_WIN + 64)             // 64
#define SM_BBLK   (SM_BIN + 64)             // 256
#define SM_BOUT   (SM_BBLK + 256)           // 80
#define SM_CC     (SM_BOUT + PO)            // 256 (ident per column)
#define SM_T1     (SM_CC + 256)             // 256 (t1 per column)
#define SM_Y1     (SM_T1 + 256)             // 256 (dim-1 spline y)
#define SM_L1     (SM_Y1 + 256)             // 256 (dim-1 spline lad)
#define SM_H      (SM_L1 + 256)             // 64*256 = 16384
#define SM_T      (SM_H + 64*COLS)          // 64*256 = 16384
#define SM_TOTALF (SM_T + 64*COLS)
#define SMEM_BYTES (SM_TOTALF * 4)          // 227136 bytes

typedef unsigned long long u64;

static __device__ __forceinline__ u64 ffma2(u64 a, u64 b, u64 c) {
    u64 d;
    asm("fma.rn.f32x2 %0, %1, %2, %3;" : "=l"(d) : "l"(a), "l"(b), "l"(c));
    return d;
}
static __device__ __forceinline__ u64 pk2(float v) {
    u64 r;
    asm("mov.b64 %0, {%1, %1};" : "=l"(r) : "f"(v));
    return r;
}
static __device__ __forceinline__ void upk2(u64 v, float& lo, float& hi) {
    asm("mov.b64 {%0, %1}, %2;" : "=f"(lo), "=f"(hi) : "l"(v));
}
static __device__ __forceinline__ float softplusf(float x) {
    return fmaxf(x, 0.0f) + log1pf(__expf(-fabsf(x)));
}

// Full rational-quadratic spline on 37 register params.
static __device__ __forceinline__ void rq_spline(const float* __restrict__ p,
                                                 float xin, float& yout, float& ladout) {
    bool inside = (xin >= -TBc) && (xin <= TBc);
    float xc = fminf(fmaxf(xin, -TBc), TBc);
    int bin = 0;
    float in_cw, in_w, in_ch, in_h;
    {   // widths (defines bin)
        float e[12]; float m = p[0];
#pragma unroll
        for (int j = 1; j < 12; ++j) m = fmaxf(m, p[j]);
        float s = 0.0f;
#pragma unroll
        for (int j = 0; j < 12; ++j) { e[j] = __expf(p[j] - m); s += e[j]; }
        float ci = 0.988f * __fdividef(1.0f, s);
#pragma unroll
        for (int j = 0; j < 12; ++j) e[j] = fmaf(e[j], ci, MINc);
        float run = 0.0f;
#pragma unroll
        for (int j = 0; j < 12; ++j) {
            run += e[j];
            float ks = (j == 11) ? (TBc + 1e-6f) : fmaf(10.0f, run, -TBc);
            if (xc >= ks) ++bin;
        }
        run = 0.0f; float prev = -TBc;
#pragma unroll
        for (int j = 0; j < 12; ++j) {
            run += e[j];
            float right = (j == 11) ? TBc : fmaf(10.0f, run, -TBc);
            if (j == bin) { in_cw = prev; in_w = right - prev; }
            prev = right;
        }
    }
    {   // heights (same bin)
        float e[12]; float m = p[12];
#pragma unroll
        for (int j = 1; j < 12; ++j) m = fmaxf(m, p[12 + j]);
        float s = 0.0f;
#pragma unroll
        for (int j = 0; j < 12; ++j) { e[j] = __expf(p[12 + j] - m); s += e[j]; }
        float ci = 0.988f * __fdividef(1.0f, s);
#pragma unroll
        for (int j = 0; j < 12; ++j) e[j] = fmaf(e[j], ci, MINc);
        float run = 0.0f; float prev = -TBc;
#pragma unroll
        for (int j = 0; j < 12; ++j) {
            run += e[j];
            float right = (j == 11) ? TBc : fmaf(10.0f, run, -TBc);
            if (j == bin) { in_ch = prev; in_h = right - prev; }
            prev = right;
        }
    }
    float uk = DCONSTf, uk1 = DCONSTf;
#pragma unroll
    for (int j = 1; j <= 12; ++j) {
        float v = p[23 + j];
        if (j == bin)     uk  = v;
        if (j == bin + 1) uk1 = v;
    }
    float dk  = MINc + softplusf(uk);
    float dk1 = MINc + softplusf(uk1);
    float invw  = __fdividef(1.0f, in_w);
    float delta = in_h * invw;
    float theta = (xc - in_cw) * invw;
    float om    = 1.0f - theta;
    float t1m   = theta * om;
    float th2   = theta * theta;
    float num   = in_h * (delta * th2 + dk * t1m);
    float den   = delta + (dk + dk1 - 2.0f * delta) * t1m;
    float yv    = in_ch + __fdividef(num, den);
    float dnum  = (delta * delta) * (dk1 * th2 + 2.0f * delta * t1m + dk * om * om);
    float lad   = __logf(dnum) - 2.0f * __logf(den);
    yout   = inside ? yv : xin;
    ladout = inside ? lad : 0.0f;
}

// ---- hidden dense layer: thread = 4 pts x 8 outs, non-dup weights ----------
template<bool ADD>
static __device__ __forceinline__ void dense_tile(const float* __restrict__ Wt,
                                                  const float* __restrict__ bias,
                                                  const float* __restrict__ inb,
                                                  float* __restrict__ dst,
                                                  int tx, int ty) {
    const int ob = 8 * ty;
    u64 acc[4][4];
#pragma unroll
    for (int q = 0; q < 4; ++q) {
        u64 b = *reinterpret_cast<const u64*>(bias + ob + 2 * q);
        acc[0][q] = b; acc[1][q] = b; acc[2][q] = b; acc[3][q] = b;
    }
    const float* cp = inb + 4 * tx;
#pragma unroll 2
    for (int k = 0; k < 64; ++k) {
        float4 a = *reinterpret_cast<const float4*>(cp + (k << 8));
        u64 r0 = pk2(fmaxf(a.x, 0.0f));
        u64 r1 = pk2(fmaxf(a.y, 0.0f));
        u64 r2 = pk2(fmaxf(a.z, 0.0f));
        u64 r3 = pk2(fmaxf(a.w, 0.0f));
        const float* wr = Wt + k * PW + ob;
        ulonglong2 wA = *reinterpret_cast<const ulonglong2*>(wr);
        ulonglong2 wB = *reinterpret_cast<const ulonglong2*>(wr + 4);
        acc[0][0] = ffma2(r0, wA.x, acc[0][0]);
        acc[1][0] = ffma2(r1, wA.x, acc[1][0]);
        acc[2][0] = ffma2(r2, wA.x, acc[2][0]);
        acc[3][0] = ffma2(r3, wA.x, acc[3][0]);
        acc[0][1] = ffma2(r0, wA.y, acc[0][1]);
        acc[1][1] = ffma2(r1, wA.y, acc[1][1]);
        acc[2][1] = ffma2(r2, wA.y, acc[2][1]);
        acc[3][1] = ffma2(r3, wA.y, acc[3][1]);
        acc[0][2] = ffma2(r0, wB.x, acc[0][2]);
        acc[1][2] = ffma2(r1, wB.x, acc[1][2]);
        acc[2][2] = ffma2(r2, wB.x, acc[2][2]);
        acc[3][2] = ffma2(r3, wB.x, acc[3][2]);
        acc[0][3] = ffma2(r0, wB.y, acc[0][3]);
        acc[1][3] = ffma2(r1, wB.y, acc[1][3]);
        acc[2][3] = ffma2(r2, wB.y, acc[2][3]);
        acc[3][3] = ffma2(r3, wB.y, acc[3][3]);
    }
#pragma unroll
    for (int q = 0; q < 4; ++q) {
        float l0, h0, l1, h1, l2, h2, l3, h3;
        upk2(acc[0][q], l0, h0); upk2(acc[1][q], l1, h1);
        upk2(acc[2][q], l2, h2); upk2(acc[3][q], l3, h3);
        float4 vlo = make_float4(l0, l1, l2, l3);
        float4 vhi = make_float4(h0, h1, h2, h3);
        float* d0 = dst + ((ob + 2 * q) << 8) + 4 * tx;
        float* d1 = dst + ((ob + 2 * q + 1) << 8) + 4 * tx;
        if (ADD) {
            float4 e0 = *reinterpret_cast<const float4*>(d0);
            float4 e1 = *reinterpret_cast<const float4*>(d1);
            vlo.x += e0.x; vlo.y += e0.y; vlo.z += e0.z; vlo.w += e0.w;
            vhi.x += e1.x; vhi.y += e1.y; vhi.z += e1.z; vhi.w += e1.w;
        }
        *reinterpret_cast<float4*>(d0) = vlo;
        *reinterpret_cast<float4*>(d1) = vhi;
    }
}

extern "C" __global__ void __launch_bounds__(THREADS, 1)
nsf_kernel(const float* __restrict__ x,
           const float* __restrict__ W_in,  const float* __restrict__ b_in,
           const float* __restrict__ W_blk, const float* __restrict__ b_blk,
           const float* __restrict__ W_out, const float* __restrict__ b_out,
           float* __restrict__ out, int n) {
    extern __shared__ float sm[];
    float* sWt  = sm + SM_WT;
    float* sWo  = sm + SM_WO;
    float* sWin = sm + SM_WIN;
    float* sbin = sm + SM_BIN;
    float* sbb  = sm + SM_BBLK;
    float* sbo  = sm + SM_BOUT;
    float* sCC  = sm + SM_CC;
    float* sT1  = sm + SM_T1;
    float* sY1  = sm + SM_Y1;
    float* sL1  = sm + SM_L1;
    float* sh   = sm + SM_H;
    float* st   = sm + SM_T;

    const int tid  = threadIdx.x;
    const int tx   = tid & 63;
    const int ty   = tid >> 6;            // 0..7
    const int col  = tid & 255;           // column for h-init / splines
    const bool grpA = (tid < 256);

    const int gidr = blockIdx.x * COLS + tid;   // only meaningful for tid<256
    const bool valid = grpA && (gidr < n);
    const int g = valid ? gidr : (n - 1);

    // point state lives in threads 0..255
    float z0 = 0.0f, z1 = 0.0f, z2 = 0.0f, lad_total = 0.0f;
    if (grpA) {
        z0 = x[3 * g + 0];
        z1 = x[3 * g + 1];
        z2 = x[3 * g + 2];
    }

    for (int it = 0; it < 8; ++it) {
        __syncthreads();   // previous transform fully consumed weights/panels

        // ---- stage this transform's weights into smem ----
        const float* gW = W_blk + it * 16384;
        for (int idx = tid; idx < 16384; idx += THREADS) {
            int l = idx >> 12, rem = idx & 4095, o = rem >> 6, k = rem & 63;
            sWt[(l * 64 + k) * PW + o] = gW[idx];
        }
        const float* gWo = W_out + it * 74 * 64;
        for (int idx = tid; idx < 74 * 64; idx += THREADS) {
            int o = idx >> 6, k = idx & 63;
            int c2 = (o < 37) ? o : (o + 3);
            sWo[k * PO + c2] = gWo[idx];
        }
        for (int idx = tid; idx < 6 * 64; idx += THREADS) {
            int pc = idx % 6, k = idx / 6;
            int c2 = (pc < 3) ? (37 + pc) : (74 + pc);
            sWo[k * PO + c2] = 0.0f;
        }
        if (tid < 64) {
            sWin[tid] = W_in[it * 64 + tid];
            sbin[tid] = b_in[it * 64 + tid];
        }
        if (tid < 256) sbb[tid] = b_blk[it * 256 + tid];
        if (tid < 74) {
            int c2 = (tid < 37) ? tid : (tid + 3);
            sbo[c2] = b_out[it * 74 + tid];
        }
        if (tid >= 74 && tid < 80) {
            int pc = tid - 74;
            int c2 = (pc < 3) ? (37 + pc) : (74 + pc);
            sbo[c2] = 0.0f;
        }

        // publish ident / t1 for group B
        float c = 0.0f, t0 = 0.0f, t1 = 0.0f;
        if (grpA) {
            c = z2; t0 = z1; t1 = z0;    // reversed z
            sCC[tid] = c;
            sT1[tid] = t1;
        }
        __syncthreads();

        // ---- h = ident * W_in + b_in  (512 threads: 32 rows each) ----
        {
            float cv = grpA ? c : sCC[col];
            int rb = grpA ? 0 : 32;
#pragma unroll 8
            for (int o = 0; o < 32; ++o) {
                int row = rb + o;
                sh[(row << 8) + col] = fmaf(cv, sWin[row], sbin[row]);
            }
        }
        __syncthreads();

        // ---- two residual blocks ----
        dense_tile<false>(sWt,            sbb,       sh, st, tx, ty); __syncthreads();
        dense_tile<true >(sWt +  64 * PW, sbb +  64, st, sh, tx, ty); __syncthreads();
        dense_tile<false>(sWt + 128 * PW, sbb + 128, sh, st, tx, ty); __syncthreads();
        dense_tile<true >(sWt + 192 * PW, sbb + 192, st, sh, tx, ty); __syncthreads();

        // ---- output layer: thread = 4 pts x 10 param cols (LDS.64 weights) ----
        {
            const int ob = 10 * ty;
            u64 acc[4][5];
#pragma unroll
            for (int q = 0; q < 5; ++q) {
                u64 b = *reinterpret_cast<const u64*>(sbo + ob + 2 * q);
                acc[0][q] = b; acc[1][q] = b; acc[2][q] = b; acc[3][q] = b;
            }
            const float* cp = sh + 4 * tx;
#pragma unroll 2
            for (int k = 0; k < 64; ++k) {
                float4 a = *reinterpret_cast<const float4*>(cp + (k << 8));
                u64 r0 = pk2(a.x), r1 = pk2(a.y), r2 = pk2(a.z), r3 = pk2(a.w);
                const float* wr = sWo + k * PO + ob;
#pragma unroll
                for (int q = 0; q < 5; ++q) {
                    u64 w = *reinterpret_cast<const u64*>(wr + 2 * q);
                    acc[0][q] = ffma2(r0, w, acc[0][q]);
                    acc[1][q] = ffma2(r1, w, acc[1][q]);
                    acc[2][q] = ffma2(r2, w, acc[2][q]);
                    acc[3][q] = ffma2(r3, w, acc[3][q]);
                }
            }
            __syncthreads();   // all reads of sh done before scatter writes sh rows

            // scatter params: padded row r -> st rows 0..63, sh rows 0..15
#pragma unroll
            for (int q = 0; q < 5; ++q) {
                float l0, h0, l1, h1, l2, h2, l3, h3;
                upk2(acc[0][q], l0, h0); upk2(acc[1][q], l1, h1);
                upk2(acc[2][q], l2, h2); upk2(acc[3][q], l3, h3);
                float4 vlo = make_float4(l0, l1, l2, l3);
                float4 vhi = make_float4(h0, h1, h2, h3);
                int r0 = ob + 2 * q, r1 = r0 + 1;
                float* p0 = (r0 < 64 ? st + (r0 << 8) : sh + ((r0 - 64) << 8)) + 4 * tx;
                float* p1 = (r1 < 64 ? st + (r1 << 8) : sh + ((r1 - 64) << 8)) + 4 * tx;
                *reinterpret_cast<float4*>(p0) = vlo;
                *reinterpret_cast<float4*>(p1) = vhi;
            }
        }
        __syncthreads();

        // ---- splines: group A does dim 0, group B does dim 1 ----
        float y0 = 0.0f, l0 = 0.0f;
        if (grpA) {
            float p[37];
#pragma unroll
            for (int r = 0; r < 37; ++r) p[r] = st[(r << 8) + col];
            rq_spline(p, t0, y0, l0);
        } else {
            float p[37];
#pragma unroll
            for (int r = 40; r < 64; ++r) p[r - 40] = st[(r << 8) + col];
#pragma unroll
            for (int r = 64; r < 77; ++r) p[r - 40] = sh[((r - 64) << 8) + col];
            float xb = sT1[col];
            float yb, lb;
            rq_spline(p, xb, yb, lb);
            sY1[col] = yb;
            sL1[col] = lb;
        }
        __syncthreads();

        if (grpA) {
            z0 = c;
            z1 = y0;
            z2 = sY1[tid];
            lad_total += l0 + sL1[tid];
        }
    }

    if (valid)
        out[gidr] = fmaf(-0.5f, z0 * z0 + z1 * z1 + z2 * z2, LOGZc + lad_total);
}

extern "C" void kernel_launch(void* const* d_in, const int* in_sizes, int n_in,
                              void* d_out, int out_size) {
    const float* x     = (const float*)d_in[0];
    const float* W_in  = (const float*)d_in[1];
    const float* b_in  = (const float*)d_in[2];
    const float* W_blk = (const float*)d_in[3];
    const float* b_blk = (const float*)d_in[4];
    const float* W_out = (const float*)d_in[5];
    const float* b_out = (const float*)d_in[6];
    float* out = (float*)d_out;

    int n = in_sizes[0] / 3;
    cudaFuncSetAttribute(nsf_kernel, cudaFuncAttributeMaxDynamicSharedMemorySize,
                         SMEM_BYTES);
    int blocks = (n + COLS - 1) / COLS;
    nsf_kernel<<<blocks, THREADS, SMEM_BYTES>>>(x, W_in, b_in, W_blk, b_blk,
                                                W_out, b_out, out, n);
}

// round 11
// speedup vs baseline: 1.6596x; 1.6596x over previous
#include <cuda_runtime.h>

// ---------------------------------------------------------------------------
// NeuralSplineFlow3D — fp32 FFMA2, 2-D tiling (4 pts x 16 outs), R8 layout
// + software-pipelined k-loops (double-buffered LDS prefetch).
// ---------------------------------------------------------------------------

#define THREADS   256
#define COLS      256
#define PW        68
#define PO        80
#define TBc       5.0f
#define MINc      0.001f
#define LOGZc     (-2.7568155996140194f)
#define DCONSTf   (0.5397424697f)

#define SM_WT     0
#define SM_WO     (SM_WT + 4*64*PW)
#define SM_WIN    (SM_WO + 64*PO)
#define SM_BIN    (SM_WIN + 64)
#define SM_BBLK   (SM_BIN + 64)
#define SM_BOUT   (SM_BBLK + 256)
#define SM_H      (SM_BOUT + PO)
#define SM_T      (SM_H + 64*COLS)
#define SM_TOTALF (SM_T + 64*COLS)
#define SMEM_BYTES (SM_TOTALF * 4)

typedef unsigned long long u64;

static __device__ __forceinline__ u64 ffma2(u64 a, u64 b, u64 c) {
    u64 d;
    asm("fma.rn.f32x2 %0, %1, %2, %3;" : "=l"(d) : "l"(a), "l"(b), "l"(c));
    return d;
}
static __device__ __forceinline__ u64 pk2(float v) {
    u64 r;
    asm("mov.b64 %0, {%1, %1};" : "=l"(r) : "f"(v));
    return r;
}
static __device__ __forceinline__ void upk2(u64 v, float& lo, float& hi) {
    asm("mov.b64 {%0, %1}, %2;" : "=f"(lo), "=f"(hi) : "l"(v));
}
static __device__ __forceinline__ float softplusf(float x) {
    return fmaxf(x, 0.0f) + log1pf(__expf(-fabsf(x)));
}

// 32 FFMA2 for one k: 4 points x 8 weight-pairs
template<bool RELU>
static __device__ __forceinline__ void fma_block(u64 acc[4][8], const float4& a,
                                                 const ulonglong2& wA, const ulonglong2& wB,
                                                 const ulonglong2& wC, const ulonglong2& wD) {
    u64 r0 = pk2(RELU ? fmaxf(a.x, 0.0f) : a.x);
    u64 r1 = pk2(RELU ? fmaxf(a.y, 0.0f) : a.y);
    u64 r2 = pk2(RELU ? fmaxf(a.z, 0.0f) : a.z);
    u64 r3 = pk2(RELU ? fmaxf(a.w, 0.0f) : a.w);
    acc[0][0] = ffma2(r0, wA.x, acc[0][0]);  acc[1][0] = ffma2(r1, wA.x, acc[1][0]);
    acc[2][0] = ffma2(r2, wA.x, acc[2][0]);  acc[3][0] = ffma2(r3, wA.x, acc[3][0]);
    acc[0][1] = ffma2(r0, wA.y, acc[0][1]);  acc[1][1] = ffma2(r1, wA.y, acc[1][1]);
    acc[2][1] = ffma2(r2, wA.y, acc[2][1]);  acc[3][1] = ffma2(r3, wA.y, acc[3][1]);
    acc[0][2] = ffma2(r0, wB.x, acc[0][2]);  acc[1][2] = ffma2(r1, wB.x, acc[1][2]);
    acc[2][2] = ffma2(r2, wB.x, acc[2][2]);  acc[3][2] = ffma2(r3, wB.x, acc[3][2]);
    acc[0][3] = ffma2(r0, wB.y, acc[0][3]);  acc[1][3] = ffma2(r1, wB.y, acc[1][3]);
    acc[2][3] = ffma2(r2, wB.y, acc[2][3]);  acc[3][3] = ffma2(r3, wB.y, acc[3][3]);
    acc[0][4] = ffma2(r0, wC.x, acc[0][4]);  acc[1][4] = ffma2(r1, wC.x, acc[1][4]);
    acc[2][4] = ffma2(r2, wC.x, acc[2][4]);  acc[3][4] = ffma2(r3, wC.x, acc[3][4]);
    acc[0][5] = ffma2(r0, wC.y, acc[0][5]);  acc[1][5] = ffma2(r1, wC.y, acc[1][5]);
    acc[2][5] = ffma2(r2, wC.y, acc[2][5]);  acc[3][5] = ffma2(r3, wC.y, acc[3][5]);
    acc[0][6] = ffma2(r0, wD.x, acc[0][6]);  acc[1][6] = ffma2(r1, wD.x, acc[1][6]);
    acc[2][6] = ffma2(r2, wD.x, acc[2][6]);  acc[3][6] = ffma2(r3, wD.x, acc[3][6]);
    acc[0][7] = ffma2(r0, wD.y, acc[0][7]);  acc[1][7] = ffma2(r1, wD.y, acc[1][7]);
    acc[2][7] = ffma2(r2, wD.y, acc[2][7]);  acc[3][7] = ffma2(r3, wD.y, acc[3][7]);
}

// ---- hidden dense layer, software-pipelined -------------------------------
template<bool ADD>
static __device__ __forceinline__ void dense_tile(const float* __restrict__ Wt,
                                                  const float* __restrict__ bias,
                                                  const float* __restrict__ inb,
                                                  float* __restrict__ dst,
                                                  int tx, int ty) {
    const int ob = 16 * ty;
    u64 acc[4][8];
#pragma unroll
    for (int q = 0; q < 8; ++q) {
        u64 b = *reinterpret_cast<const u64*>(bias + ob + 2 * q);
        acc[0][q] = b; acc[1][q] = b; acc[2][q] = b; acc[3][q] = b;
    }
    const float* cp = inb + 4 * tx;
    const float* wp = Wt + ob;
    float4 a = *reinterpret_cast<const float4*>(cp);
    ulonglong2 wA = *reinterpret_cast<const ulonglong2*>(wp);
    ulonglong2 wB = *reinterpret_cast<const ulonglong2*>(wp + 4);
    ulonglong2 wC = *reinterpret_cast<const ulonglong2*>(wp + 8);
    ulonglong2 wD = *reinterpret_cast<const ulonglong2*>(wp + 12);
#pragma unroll 3
    for (int k = 0; k < 63; ++k) {
        float4 an = *reinterpret_cast<const float4*>(cp + ((k + 1) << 8));
        const float* wr = wp + (k + 1) * PW;
        ulonglong2 nA = *reinterpret_cast<const ulonglong2*>(wr);
        ulonglong2 nB = *reinterpret_cast<const ulonglong2*>(wr + 4);
        ulonglong2 nC = *reinterpret_cast<const ulonglong2*>(wr + 8);
        ulonglong2 nD = *reinterpret_cast<const ulonglong2*>(wr + 12);
        fma_block<true>(acc, a, wA, wB, wC, wD);
        a = an; wA = nA; wB = nB; wC = nC; wD = nD;
    }
    fma_block<true>(acc, a, wA, wB, wC, wD);   // k = 63

#pragma unroll
    for (int q = 0; q < 8; ++q) {
        float l0, h0, l1, h1, l2, h2, l3, h3;
        upk2(acc[0][q], l0, h0); upk2(acc[1][q], l1, h1);
        upk2(acc[2][q], l2, h2); upk2(acc[3][q], l3, h3);
        float4 vlo = make_float4(l0, l1, l2, l3);
        float4 vhi = make_float4(h0, h1, h2, h3);
        float* d0 = dst + ((ob + 2 * q) << 8) + 4 * tx;
        float* d1 = dst + ((ob + 2 * q + 1) << 8) + 4 * tx;
        if (ADD) {
            float4 e0 = *reinterpret_cast<const float4*>(d0);
            float4 e1 = *reinterpret_cast<const float4*>(d1);
            vlo.x += e0.x; vlo.y += e0.y; vlo.z += e0.z; vlo.w += e0.w;
            vhi.x += e1.x; vhi.y += e1.y; vhi.z += e1.z; vhi.w += e1.w;
        }
        *reinterpret_cast<float4*>(d0) = vlo;
        *reinterpret_cast<float4*>(d1) = vhi;
    }
}

extern "C" __global__ void __launch_bounds__(THREADS, 1)
nsf_kernel(const float* __restrict__ x,
           const float* __restrict__ W_in,  const float* __restrict__ b_in,
           const float* __restrict__ W_blk, const float* __restrict__ b_blk,
           const float* __restrict__ W_out, const float* __restrict__ b_out,
           float* __restrict__ out, int n) {
    extern __shared__ float sm[];
    float* sWt  = sm + SM_WT;
    float* sWo  = sm + SM_WO;
    float* sWin = sm + SM_WIN;
    float* sbin = sm + SM_BIN;
    float* sbb  = sm + SM_BBLK;
    float* sbo  = sm + SM_BOUT;
    float* sh   = sm + SM_H;
    float* st   = sm + SM_T;

    const int tid = threadIdx.x;
    const int tx  = tid & 63;
    const int ty  = tid >> 6;

    const int gidr = blockIdx.x * COLS + tid;
    const bool valid = (gidr < n);
    const int g = valid ? gidr : (n - 1);

    float z0 = x[3 * g + 0];
    float z1 = x[3 * g + 1];
    float z2 = x[3 * g + 2];
    float lad_total = 0.0f;

    for (int it = 0; it < 8; ++it) {
        __syncthreads();

        const float* gW = W_blk + it * 16384;
        for (int idx = tid; idx < 16384; idx += THREADS) {
            int l = idx >> 12, rem = idx & 4095, o = rem >> 6, k = rem & 63;
            sWt[(l * 64 + k) * PW + o] = gW[idx];
        }
        const float* gWo = W_out + it * 74 * 64;
        for (int idx = tid; idx < 74 * 64; idx += THREADS) {
            int o = idx >> 6, k = idx & 63;
            int col = (o < 37) ? o : (o + 3);
            sWo[k * PO + col] = gWo[idx];
        }
        for (int idx = tid; idx < 6 * 64; idx += THREADS) {
            int pc = idx % 6, k = idx / 6;
            int col = (pc < 3) ? (37 + pc) : (74 + pc);
            sWo[k * PO + col] = 0.0f;
        }
        if (tid < 64) {
            sWin[tid] = W_in[it * 64 + tid];
            sbin[tid] = b_in[it * 64 + tid];
        }
        sbb[tid] = b_blk[it * 256 + tid];
        if (tid < 74) {
            int col = (tid < 37) ? tid : (tid + 3);
            sbo[col] = b_out[it * 74 + tid];
        }
        if (tid >= 74 && tid < 80) {
            int pc = tid - 74;
            int col = (pc < 3) ? (37 + pc) : (74 + pc);
            sbo[col] = 0.0f;
        }
        __syncthreads();

        float c = z2, t0 = z1, t1 = z0;

#pragma unroll 8
        for (int o = 0; o < 64; ++o)
            sh[(o << 8) + tid] = fmaf(c, sWin[o], sbin[o]);
        __syncthreads();

        dense_tile<false>(sWt,            sbb,       sh, st, tx, ty); __syncthreads();
        dense_tile<true >(sWt +  64 * PW, sbb +  64, st, sh, tx, ty); __syncthreads();
        dense_tile<false>(sWt + 128 * PW, sbb + 128, sh, st, tx, ty); __syncthreads();
        dense_tile<true >(sWt + 192 * PW, sbb + 192, st, sh, tx, ty); __syncthreads();

        // ---- output layer: 4 pts x 20 cols, pipelined (5 x LDS.64 weights) ----
        {
            const int ob = 20 * ty;
            u64 acc[4][10];
#pragma unroll
            for (int q = 0; q < 10; ++q) {
                u64 b = *reinterpret_cast<const u64*>(sbo + ob + 2 * q);
                acc[0][q] = b; acc[1][q] = b; acc[2][q] = b; acc[3][q] = b;
            }
            const float* cp = sh + 4 * tx;
            const float* wp = sWo + ob;
            float4 a = *reinterpret_cast<const float4*>(cp);
            u64 w0 = *reinterpret_cast<const u64*>(wp);
            u64 w1 = *reinterpret_cast<const u64*>(wp + 2);
            u64 w2 = *reinterpret_cast<const u64*>(wp + 4);
            u64 w3 = *reinterpret_cast<const u64*>(wp + 6);
            u64 w4 = *reinterpret_cast<const u64*>(wp + 8);
            u64 w5 = *reinterpret_cast<const u64*>(wp + 10);
            u64 w6 = *reinterpret_cast<const u64*>(wp + 12);
            u64 w7 = *reinterpret_cast<const u64*>(wp + 14);
            u64 w8 = *reinterpret_cast<const u64*>(wp + 16);
            u64 w9 = *reinterpret_cast<const u64*>(wp + 18);
#pragma unroll 3
            for (int k = 0; k < 64; ++k) {
                float4 an;
                u64 n0, n1, n2, n3, n4, n5, n6, n7, n8, n9;
                if (k < 63) {
                    an = *reinterpret_cast<const float4*>(cp + ((k + 1) << 8));
                    const float* wr = wp + (k + 1) * PO;
                    n0 = *reinterpret_cast<const u64*>(wr);
                    n1 = *reinterpret_cast<const u64*>(wr + 2);
                    n2 = *reinterpret_cast<const u64*>(wr + 4);
                    n3 = *reinterpret_cast<const u64*>(wr + 6);
                    n4 = *reinterpret_cast<const u64*>(wr + 8);
                    n5 = *reinterpret_cast<const u64*>(wr + 10);
                    n6 = *reinterpret_cast<const u64*>(wr + 12);
                    n7 = *reinterpret_cast<const u64*>(wr + 14);
                    n8 = *reinterpret_cast<const u64*>(wr + 16);
                    n9 = *reinterpret_cast<const u64*>(wr + 18);
                }
                u64 r0 = pk2(a.x), r1 = pk2(a.y), r2 = pk2(a.z), r3 = pk2(a.w);
                acc[0][0] = ffma2(r0, w0, acc[0][0]); acc[1][0] = ffma2(r1, w0, acc[1][0]);
                acc[2][0] = ffma2(r2, w0, acc[2][0]); acc[3][0] = ffma2(r3, w0, acc[3][0]);
                acc[0][1] = ffma2(r0, w1, acc[0][1]); acc[1][1] = ffma2(r1, w1, acc[1][1]);
                acc[2][1] = ffma2(r2, w1, acc[2][1]); acc[3][1] = ffma2(r3, w1, acc[3][1]);
                acc[0][2] = ffma2(r0, w2, acc[0][2]); acc[1][2] = ffma2(r1, w2, acc[1][2]);
                acc[2][2] = ffma2(r2, w2, acc[2][2]); acc[3][2] = ffma2(r3, w2, acc[3][2]);
                acc[0][3] = ffma2(r0, w3, acc[0][3]); acc[1][3] = ffma2(r1, w3, acc[1][3]);
                acc[2][3] = ffma2(r2, w3, acc[2][3]); acc[3][3] = ffma2(r3, w3, acc[3][3]);
                acc[0][4] = ffma2(r0, w4, acc[0][4]); acc[1][4] = ffma2(r1, w4, acc[1][4]);
                acc[2][4] = ffma2(r2, w4, acc[2][4]); acc[3][4] = ffma2(r3, w4, acc[3][4]);
                acc[0][5] = ffma2(r0, w5, acc[0][5]); acc[1][5] = ffma2(r1, w5, acc[1][5]);
                acc[2][5] = ffma2(r2, w5, acc[2][5]); acc[3][5] = ffma2(r3, w5, acc[3][5]);
                acc[0][6] = ffma2(r0, w6, acc[0][6]); acc[1][6] = ffma2(r1, w6, acc[1][6]);
                acc[2][6] = ffma2(r2, w6, acc[2][6]); acc[3][6] = ffma2(r3, w6, acc[3][6]);
                acc[0][7] = ffma2(r0, w7, acc[0][7]); acc[1][7] = ffma2(r1, w7, acc[1][7]);
                acc[2][7] = ffma2(r2, w7, acc[2][7]); acc[3][7] = ffma2(r3, w7, acc[3][7]);
                acc[0][8] = ffma2(r0, w8, acc[0][8]); acc[1][8] = ffma2(r1, w8, acc[1][8]);
                acc[2][8] = ffma2(r2, w8, acc[2][8]); acc[3][8] = ffma2(r3, w8, acc[3][8]);
                acc[0][9] = ffma2(r0, w9, acc[0][9]); acc[1][9] = ffma2(r1, w9, acc[1][9]);
                acc[2][9] = ffma2(r2, w9, acc[2][9]); acc[3][9] = ffma2(r3, w9, acc[3][9]);
                if (k < 63) {
                    a = an;
                    w0 = n0; w1 = n1; w2 = n2; w3 = n3; w4 = n4;
                    w5 = n5; w6 = n6; w7 = n7; w8 = n8; w9 = n9;
                }
            }
            __syncthreads();

#pragma unroll
            for (int q = 0; q < 10; ++q) {
                float l0, h0, l1, h1, l2, h2, l3, h3;
                upk2(acc[0][q], l0, h0); upk2(acc[1][q], l1, h1);
                upk2(acc[2][q], l2, h2); upk2(acc[3][q], l3, h3);
                float4 vlo = make_float4(l0, l1, l2, l3);
                float4 vhi = make_float4(h0, h1, h2, h3);
                int r0 = ob + 2 * q, r1 = r0 + 1;
                float* p0 = (r0 < 64 ? st + (r0 << 8) : sh + ((r0 - 64) << 8)) + 4 * tx;
                float* p1 = (r1 < 64 ? st + (r1 << 8) : sh + ((r1 - 64) << 8)) + 4 * tx;
                *reinterpret_cast<float4*>(p0) = vlo;
                *reinterpret_cast<float4*>(p1) = vhi;
            }
        }
        __syncthreads();

        // ---- splines ----
        float y0, l0, y1, l1;
        {
            float p[37];
#pragma unroll
            for (int r = 0; r < 37; ++r) p[r] = st[(r << 8) + tid];
            bool inside = (t0 >= -TBc) && (t0 <= TBc);
            float xc = fminf(fmaxf(t0, -TBc), TBc);
            int bin = 0;
            float in_cw, in_w, in_ch, in_h;
            {
                float e[12]; float m = p[0];
#pragma unroll
                for (int j = 1; j < 12; ++j) m = fmaxf(m, p[j]);
                float s = 0.0f;
#pragma unroll
                for (int j = 0; j < 12; ++j) { e[j] = __expf(p[j] - m); s += e[j]; }
                float ci = 0.988f * __fdividef(1.0f, s);
#pragma unroll
                for (int j = 0; j < 12; ++j) e[j] = fmaf(e[j], ci, MINc);
                float run = 0.0f;
#pragma unroll
                for (int j = 0; j < 12; ++j) {
                    run += e[j];
                    float ks = (j == 11) ? (TBc + 1e-6f) : fmaf(10.0f, run, -TBc);
                    if (xc >= ks) ++bin;
                }
                run = 0.0f; float prev = -TBc;
#pragma unroll
                for (int j = 0; j < 12; ++j) {
                    run += e[j];
                    float right = (j == 11) ? TBc : fmaf(10.0f, run, -TBc);
                    if (j == bin) { in_cw = prev; in_w = right - prev; }
                    prev = right;
                }
            }
            {
                float e[12]; float m = p[12];
#pragma unroll
                for (int j = 1; j < 12; ++j) m = fmaxf(m, p[12 + j]);
                float s = 0.0f;
#pragma unroll
                for (int j = 0; j < 12; ++j) { e[j] = __expf(p[12 + j] - m); s += e[j]; }
                float ci = 0.988f * __fdividef(1.0f, s);
#pragma unroll
                for (int j = 0; j < 12; ++j) e[j] = fmaf(e[j], ci, MINc);
                float run = 0.0f; float prev = -TBc;
#pragma unroll
                for (int j = 0; j < 12; ++j) {
                    run += e[j];
                    float right = (j == 11) ? TBc : fmaf(10.0f, run, -TBc);
                    if (j == bin) { in_ch = prev; in_h = right - prev; }
                    prev = right;
                }
            }
            float uk = DCONSTf, uk1 = DCONSTf;
#pragma unroll
            for (int j = 1; j <= 12; ++j) {
                float v = p[23 + j];
                if (j == bin)     uk  = v;
                if (j == bin + 1) uk1 = v;
            }
            float dk  = MINc + softplusf(uk);
            float dk1 = MINc + softplusf(uk1);
            float invw  = __fdividef(1.0f, in_w);
            float delta = in_h * invw;
            float theta = (xc - in_cw) * invw;
            float om    = 1.0f - theta;
            float t1m   = theta * om;
            float th2   = theta * theta;
            float num   = in_h * (delta * th2 + dk * t1m);
            float den   = delta + (dk + dk1 - 2.0f * delta) * t1m;
            float yv    = in_ch + __fdividef(num, den);
            float dnum  = (delta * delta) * (dk1 * th2 + 2.0f * delta * t1m + dk * om * om);
            float lad   = __logf(dnum) - 2.0f * __logf(den);
            y0 = inside ? yv : t0;
            l0 = inside ? lad : 0.0f;
        }
        {
            float p[37];
#pragma unroll
            for (int r = 40; r < 64; ++r) p[r - 40] = st[(r << 8) + tid];
#pragma unroll
            for (int r = 64; r < 77; ++r) p[r - 40] = sh[((r - 64) << 8) + tid];
            bool inside = (t1 >= -TBc) && (t1 <= TBc);
            float xc = fminf(fmaxf(t1, -TBc), TBc);
            int bin = 0;
            float in_cw, in_w, in_ch, in_h;
            {
                float e[12]; float m = p[0];
#pragma unroll
                for (int j = 1; j < 12; ++j) m = fmaxf(m, p[j]);
                float s = 0.0f;
#pragma unroll
                for (int j = 0; j < 12; ++j) { e[j] = __expf(p[j] - m); s += e[j]; }
                float ci = 0.988f * __fdividef(1.0f, s);
#pragma unroll
                for (int j = 0; j < 12; ++j) e[j] = fmaf(e[j], ci, MINc);
                float run = 0.0f;
#pragma unroll
                for (int j = 0; j < 12; ++j) {
                    run += e[j];
                    float ks = (j == 11) ? (TBc + 1e-6f) : fmaf(10.0f, run, -TBc);
                    if (xc >= ks) ++bin;
                }
                run = 0.0f; float prev = -TBc;
#pragma unroll
                for (int j = 0; j < 12; ++j) {
                    run += e[j];
                    float right = (j == 11) ? TBc : fmaf(10.0f, run, -TBc);
                    if (j == bin) { in_cw = prev; in_w = right - prev; }
                    prev = right;
                }
            }
            {
                float e[12]; float m = p[12];
#pragma unroll
                for (int j = 1; j < 12; ++j) m = fmaxf(m, p[12 + j]);
                float s = 0.0f;
#pragma unroll
                for (int j = 0; j < 12; ++j) { e[j] = __expf(p[12 + j] - m); s += e[j]; }
                float ci = 0.988f * __fdividef(1.0f, s);
#pragma unroll
                for (int j = 0; j < 12; ++j) e[j] = fmaf(e[j], ci, MINc);
                float run = 0.0f; float prev = -TBc;
#pragma unroll
                for (int j = 0; j < 12; ++j) {
                    run += e[j];
                    float right = (j == 11) ? TBc : fmaf(10.0f, run, -TBc);
                    if (j == bin) { in_ch = prev; in_h = right - prev; }
                    prev = right;
                }
            }
            float uk = DCONSTf, uk1 = DCONSTf;
#pragma unroll
            for (int j = 1; j <= 12; ++j) {
                float v = p[23 + j];
                if (j == bin)     uk  = v;
                if (j == bin + 1) uk1 = v;
            }
            float dk  = MINc + softplusf(uk);
            float dk1 = MINc + softplusf(uk1);
            float invw  = __fdividef(1.0f, in_w);
            float delta = in_h * invw;
            float theta = (xc - in_cw) * invw;
            float om    = 1.0f - theta;
            float t1m   = theta * om;
            float th2   = theta * theta;
            float num   = in_h * (delta * th2 + dk * t1m);
            float den   = delta + (dk + dk1 - 2.0f * delta) * t1m;
            float yv    = in_ch + __fdividef(num, den);
            float dnum  = (delta * delta) * (dk1 * th2 + 2.0f * delta * t1m + dk * om * om);
            float lad   = __logf(dnum) - 2.0f * __logf(den);
            y1 = inside ? yv : t1;
            l1 = inside ? lad : 0.0f;
        }

        z0 = c; z1 = y0; z2 = y1;
        lad_total += l0 + l1;
    }

    if (valid)
        out[gidr] = fmaf(-0.5f, z0 * z0 + z1 * z1 + z2 * z2, LOGZc + lad_total);
}

extern "C" void kernel_launch(void* const* d_in, const int* in_sizes, int n_in,
                              void* d_out, int out_size) {
    const float* x     = (const float*)d_in[0];
    const float* W_in  = (const float*)d_in[1];
    const float* b_in  = (const float*)d_in[2];
    const float* W_blk = (const float*)d_in[3];
    const float* b_blk = (const float*)d_in[4];
    const float* W_out = (const float*)d_in[5];
    const float* b_out = (const float*)d_in[6];
    float* out = (float*)d_out;

    int n = in_sizes[0] / 3;
    cudaFuncSetAttribute(nsf_kernel, cudaFuncAttributeMaxDynamicSharedMemorySize,
                         SMEM_BYTES);
    int blocks = (n + COLS - 1) / COLS;
    nsf_kernel<<<blocks, THREADS, SMEM_BYTES>>>(x, W_in, b_in, W_blk, b_blk,
                                                W_out, b_out, out, n);
}